// round 5
// baseline (speedup 1.0000x reference)
#include <cuda_runtime.h>
#include <cuda_fp16.h>
#include <cstdint>
#include <cstddef>

#define NROWS 65536
#define PLANE ((size_t)NROWS * 256)

__device__ __align__(128) __half g_xh [6 * PLANE];
__device__ __align__(128) __half g_q0h[3 * PLANE];
__device__ __align__(128) __half g_qa [3 * PLANE];
__device__ __align__(128) __half g_qb [3 * PLANE];
__device__ __align__(128) __half g_wcat[3 * 256 * 768];

#define SWZ(x) ((x) ^ (((x) >> 3) & 0x70))

// SMEM: bias 1KB, 3x A bufs (16KB), 3x B bufs (16KB)
#define OFF_BIAS 0
#define OFF_A    1024
#define OFF_B    (1024 + 3 * 16384)
#define SMEM_TOTAL (1024 + 6 * 16384)   // 99328

__device__ __forceinline__ uint32_t s2u(const void* p) {
    return (uint32_t)__cvta_generic_to_shared(p);
}

#define CPA(dst, src) \
    asm volatile("cp.async.cg.shared.global [%0], [%1], 16;" \
                 :: "r"(dst), "l"(src) : "memory")
#define CPC() asm volatile("cp.async.commit_group;" ::: "memory")
#define CPW1() asm volatile("cp.async.wait_group 1;" ::: "memory")

#define LDSM4(r, addr) \
    asm volatile("ldmatrix.sync.aligned.m8n8.x4.shared.b16 {%0,%1,%2,%3}, [%4];" \
                 : "=r"((r)[0]), "=r"((r)[1]), "=r"((r)[2]), "=r"((r)[3]) \
                 : "r"(addr))

#define MMA(cr, av, b0v, b1v) \
    asm volatile("mma.sync.aligned.m16n8k16.row.col.f32.f16.f16.f32 " \
                 "{%0,%1,%2,%3}, {%4,%5,%6,%7}, {%8,%9}, {%0,%1,%2,%3};" \
                 : "+f"((cr)[0]), "+f"((cr)[1]), "+f"((cr)[2]), "+f"((cr)[3]) \
                 : "r"((av)[0]), "r"((av)[1]), "r"((av)[2]), "r"((av)[3]), \
                   "r"(b0v), "r"(b1v))

// ---------------- prep kernels ---------------------------------------------
__global__ void prep_xq_kernel(const float* __restrict__ x,
                               const float* __restrict__ q) {
    size_t idx = (size_t)blockIdx.x * 256 + threadIdx.x;
    const float2* p = reinterpret_cast<const float2*>(x + idx * 6);
    float2 a = p[0], b = p[1], c = p[2];
    g_xh[0 * PLANE + idx] = __float2half(a.x);
    g_xh[1 * PLANE + idx] = __float2half(a.y);
    g_xh[2 * PLANE + idx] = __float2half(b.x);
    g_xh[3 * PLANE + idx] = __float2half(b.y);
    g_xh[4 * PLANE + idx] = __float2half(c.x);
    g_xh[5 * PLANE + idx] = __float2half(c.y);
    g_q0h[0 * PLANE + idx] = __float2half(q[idx * 3 + 0]);
    g_q0h[1 * PLANE + idx] = __float2half(q[idx * 3 + 1]);
    g_q0h[2 * PLANE + idx] = __float2half(q[idx * 3 + 2]);
}
__global__ void prep_w_kernel(const float* __restrict__ W1,
                              const float* __restrict__ W2,
                              const float* __restrict__ W3) {
    uint32_t t = blockIdx.x * 256 + threadIdx.x;   // 3*256*768 = 589824
    int l = t / 196608, r = t % 196608;
    int o = r / 768, k = r % 768;
    int j = k >> 8, c = k & 255;
    const float* W = (l == 0) ? W1 : (l == 1 ? W2 : W3);
    g_wcat[t] = __float2half(W[(o * 256 + c) * 3 + j]);
}

// ---------------- layer kernel ---------------------------------------------
// grid: (2 n-halves, 512 row-tiles, 3 groups), 256 threads
template <bool FINAL>
__global__ void __launch_bounds__(256, 2)
layer_kernel(int qin_sel, int qout_sel, const float* __restrict__ bias,
             int layer, const float* __restrict__ qres, float* __restrict__ out) {
    extern __shared__ char smem[];
    const int tid   = threadIdx.x;
    const int lane  = tid & 31;
    const int wid   = tid >> 5;
    const int warpM = wid & 3;       // 4 warps in M (32 rows each)
    const int warpN = wid >> 2;      // 2 warps in N (64 cols each)
    const int half  = blockIdx.x;
    const int row0  = blockIdx.y * 128;
    const int g     = blockIdx.z;
    const int ncta  = half * 128;

    const __half* __restrict__ qin =
        (qin_sel == 0) ? g_q0h : (qin_sel == 1 ? g_qa : g_qb);
    __half* __restrict__ qout = (qout_sel == 1) ? g_qa : g_qb;
    const __half* __restrict__ wc = g_wcat + (size_t)layer * (256 * 768);

    float* bias_s = reinterpret_cast<float*>(smem + OFF_BIAS);
    if (tid < 128) bias_s[tid] = bias[ncta + tid];

    const uint32_t sb = s2u(smem);

    // chunk loader: chunk i covers k in [64i, 64i+64), destination buffer bsel
    auto loadChunk = [&](int i, int bsel) {
        const int j  = i >> 2;
        const int c0 = (i & 3) * 64;
        const __half* sA = ((j < 2) ? (g_xh + (size_t)(2 * g + j) * PLANE)
                                    : (qin + (size_t)g * PLANE))
                         + (size_t)row0 * 256 + c0;
        const uint32_t dA = sb + OFF_A + bsel * 16384;
        #pragma unroll
        for (int it = 0; it < 4; ++it) {           // A: 128 rows x 128B
            int v = tid + it * 256, m = v >> 3, t16 = v & 7;
            CPA(dA + SWZ(m * 128 + t16 * 16), sA + (size_t)m * 256 + t16 * 8);
        }
        const __half* sB = wc + (size_t)ncta * 768 + i * 64;
        const uint32_t dB = sb + OFF_B + bsel * 16384;
        #pragma unroll
        for (int it = 0; it < 4; ++it) {           // B: 128 n-rows x 128B
            int v = tid + it * 256, n = v >> 3, t16 = v & 7;
            CPA(dB + SWZ(n * 128 + t16 * 16), sB + (size_t)n * 768 + t16 * 8);
        }
    };

    float c[2][8][4];
    #pragma unroll
    for (int mt = 0; mt < 2; ++mt)
        #pragma unroll
        for (int j = 0; j < 8; ++j)
            #pragma unroll
            for (int e = 0; e < 4; ++e) c[mt][j][e] = 0.0f;

    loadChunk(0, 0); CPC();
    loadChunk(1, 1); CPC();

    #pragma unroll 1
    for (int i = 0; i < 12; ++i) {
        const int bsel = i % 3;
        CPW1();                 // chunk i resident (newest pending may be i+1)
        __syncthreads();        // all warps done with buffer (i-1)%3 == (i+2)%3
        if (i + 2 < 12) loadChunk(i + 2, (i + 2) % 3);
        CPC();                  // unconditional: keeps group accounting uniform

        const uint32_t aoff = sb + OFF_A + bsel * 16384;
        const uint32_t boff = sb + OFF_B + bsel * 16384;
        #pragma unroll
        for (int ks = 0; ks < 4; ++ks) {
            const int k0 = ks * 16;
            uint32_t a[2][4];
            #pragma unroll
            for (int mt = 0; mt < 2; ++mt) {
                int r  = warpM * 32 + mt * 16 + (lane & 15);
                int kb = k0 + ((lane >> 4) << 3);
                LDSM4(a[mt], aoff + SWZ(r * 128 + kb * 2));
            }
            uint32_t b[4][4];
            #pragma unroll
            for (int j = 0; j < 4; ++j) {
                int n  = warpN * 64 + j * 16 + ((lane >> 3) & 2) * 4 + (lane & 7);
                int kb = k0 + ((lane >> 3) & 1) * 8;
                LDSM4(b[j], boff + SWZ(n * 128 + kb * 2));
            }
            #pragma unroll
            for (int mt = 0; mt < 2; ++mt)
                #pragma unroll
                for (int j = 0; j < 4; ++j) {
                    MMA(c[mt][2 * j],     a[mt], b[j][0], b[j][1]);
                    MMA(c[mt][2 * j + 1], a[mt], b[j][2], b[j][3]);
                }
        }
    }

    // epilogue
    __half* plane = qout + (size_t)g * PLANE;
    #pragma unroll
    for (int mt = 0; mt < 2; ++mt) {
        const int r0 = row0 + warpM * 32 + mt * 16 + (lane >> 2);
        #pragma unroll
        for (int j = 0; j < 8; ++j) {
            const int cl = warpN * 64 + j * 8 + (lane & 3) * 2;
            const float b0 = bias_s[cl], b1 = bias_s[cl + 1];
            float v0 = c[mt][j][0] + b0, v1 = c[mt][j][1] + b1;
            float v2 = c[mt][j][2] + b0, v3 = c[mt][j][3] + b1;
            const int gc = ncta + cl;
            if (FINAL) {
                // residual + relu + interleaved fp32 store: out[n*768 + c*3 + g]
                size_t base0 = (size_t)r0 * 768 + (size_t)gc * 3 + g;
                size_t base1 = base0 + (size_t)8 * 768;
                out[base0]     = fmaxf(v0 + __ldg(qres + base0),     0.0f);
                out[base0 + 3] = fmaxf(v1 + __ldg(qres + base0 + 3), 0.0f);
                out[base1]     = fmaxf(v2 + __ldg(qres + base1),     0.0f);
                out[base1 + 3] = fmaxf(v3 + __ldg(qres + base1 + 3), 0.0f);
            } else {
                v0 = fmaxf(v0, 0.0f); v1 = fmaxf(v1, 0.0f);
                v2 = fmaxf(v2, 0.0f); v3 = fmaxf(v3, 0.0f);
                *reinterpret_cast<__half2*>(plane + (size_t)r0 * 256 + gc) =
                    __floats2half2_rn(v0, v1);
                *reinterpret_cast<__half2*>(plane + (size_t)(r0 + 8) * 256 + gc) =
                    __floats2half2_rn(v2, v3);
            }
        }
    }
}

// ---------------- launch ---------------------------------------------------
extern "C" void kernel_launch(void* const* d_in, const int* in_sizes, int n_in,
                              void* d_out, int out_size) {
    const float* x  = (const float*)d_in[0];
    const float* q  = (const float*)d_in[1];
    const float* W1 = (const float*)d_in[2];
    const float* b1 = (const float*)d_in[3];
    const float* W2 = (const float*)d_in[4];
    const float* b2 = (const float*)d_in[5];
    const float* W3 = (const float*)d_in[6];
    const float* b3 = (const float*)d_in[7];
    float* out = (float*)d_out;

    cudaFuncSetAttribute(layer_kernel<false>,
                         cudaFuncAttributeMaxDynamicSharedMemorySize, SMEM_TOTAL);
    cudaFuncSetAttribute(layer_kernel<true>,
                         cudaFuncAttributeMaxDynamicSharedMemorySize, SMEM_TOTAL);

    prep_xq_kernel<<<NROWS, 256>>>(x, q);
    prep_w_kernel<<<2304, 256>>>(W1, W2, W3);

    dim3 grid(2, 512, 3);
    layer_kernel<false><<<grid, 256, SMEM_TOTAL>>>(0, 1, b1, 0, nullptr, nullptr);
    layer_kernel<false><<<grid, 256, SMEM_TOTAL>>>(1, 2, b2, 1, nullptr, nullptr);
    layer_kernel<true> <<<grid, 256, SMEM_TOTAL>>>(2, 0, b3, 2, q, out);
}

// round 6
// speedup vs baseline: 1.2063x; 1.2063x over previous
#include <cuda_runtime.h>
#include <cuda_fp16.h>
#include <cstdint>
#include <cstddef>

#define NROWS 65536
#define PLANE ((size_t)NROWS * 256)

__device__ __align__(128) __half g_xh [6 * PLANE];
__device__ __align__(128) __half g_q0h[3 * PLANE];
__device__ __align__(128) __half g_qa [3 * PLANE];
__device__ __align__(128) __half g_qb [3 * PLANE];
__device__ __align__(128) __half g_wcat[3 * 256 * 768];

#define SWZ(x) ((x) ^ (((x) >> 3) & 0x70))

// SMEM: bias 1KB, 3x A bufs (16KB), 3x B bufs (16KB)
#define OFF_BIAS 0
#define OFF_A    1024
#define OFF_B    (1024 + 3 * 16384)
#define SMEM_TOTAL (1024 + 6 * 16384)   // 99328

__device__ __forceinline__ uint32_t s2u(const void* p) {
    return (uint32_t)__cvta_generic_to_shared(p);
}

#define CPA(dst, src) \
    asm volatile("cp.async.cg.shared.global [%0], [%1], 16;" \
                 :: "r"(dst), "l"(src) : "memory")
#define CPC() asm volatile("cp.async.commit_group;" ::: "memory")
#define CPW1() asm volatile("cp.async.wait_group 1;" ::: "memory")

#define LDSM4(r, addr) \
    asm volatile("ldmatrix.sync.aligned.m8n8.x4.shared.b16 {%0,%1,%2,%3}, [%4];" \
                 : "=r"((r)[0]), "=r"((r)[1]), "=r"((r)[2]), "=r"((r)[3]) \
                 : "r"(addr))

#define MMA(cr, av, b0v, b1v) \
    asm volatile("mma.sync.aligned.m16n8k16.row.col.f32.f16.f16.f32 " \
                 "{%0,%1,%2,%3}, {%4,%5,%6,%7}, {%8,%9}, {%0,%1,%2,%3};" \
                 : "+f"((cr)[0]), "+f"((cr)[1]), "+f"((cr)[2]), "+f"((cr)[3]) \
                 : "r"((av)[0]), "r"((av)[1]), "r"((av)[2]), "r"((av)[3]), \
                   "r"(b0v), "r"(b1v))

// ---------------- prep kernels ---------------------------------------------
__global__ void prep_xq_kernel(const float* __restrict__ x,
                               const float* __restrict__ q) {
    size_t idx = (size_t)blockIdx.x * 256 + threadIdx.x;
    const float2* p = reinterpret_cast<const float2*>(x + idx * 6);
    float2 a = p[0], b = p[1], c = p[2];
    g_xh[0 * PLANE + idx] = __float2half(a.x);
    g_xh[1 * PLANE + idx] = __float2half(a.y);
    g_xh[2 * PLANE + idx] = __float2half(b.x);
    g_xh[3 * PLANE + idx] = __float2half(b.y);
    g_xh[4 * PLANE + idx] = __float2half(c.x);
    g_xh[5 * PLANE + idx] = __float2half(c.y);
    g_q0h[0 * PLANE + idx] = __float2half(q[idx * 3 + 0]);
    g_q0h[1 * PLANE + idx] = __float2half(q[idx * 3 + 1]);
    g_q0h[2 * PLANE + idx] = __float2half(q[idx * 3 + 2]);
}
__global__ void prep_w_kernel(const float* __restrict__ W1,
                              const float* __restrict__ W2,
                              const float* __restrict__ W3) {
    uint32_t t = blockIdx.x * 256 + threadIdx.x;   // 3*256*768 = 589824
    int l = t / 196608, r = t % 196608;
    int o = r / 768, k = r % 768;
    int j = k >> 8, c = k & 255;
    const float* W = (l == 0) ? W1 : (l == 1 ? W2 : W3);
    g_wcat[t] = __float2half(W[(o * 256 + c) * 3 + j]);
}

// ---------------- layer kernel ---------------------------------------------
// grid: (2 n-halves, 512 row-tiles, 3 groups), 256 threads
__global__ void __launch_bounds__(256, 2)
layer_kernel(int qin_sel, int qout_sel, const float* __restrict__ bias, int layer) {
    extern __shared__ char smem[];
    const int tid   = threadIdx.x;
    const int lane  = tid & 31;
    const int wid   = tid >> 5;
    const int warpM = wid & 3;       // 4 warps in M (32 rows each)
    const int warpN = wid >> 2;      // 2 warps in N (64 cols each)
    const int half  = blockIdx.x;
    const int row0  = blockIdx.y * 128;
    const int g     = blockIdx.z;
    const int ncta  = half * 128;

    const __half* __restrict__ qin =
        (qin_sel == 0) ? g_q0h : (qin_sel == 1 ? g_qa : g_qb);
    __half* __restrict__ qout = (qout_sel == 1) ? g_qa : g_qb;
    const __half* __restrict__ wc = g_wcat + (size_t)layer * (256 * 768);

    // A-plane source table
    const __half* aplane[3];
    aplane[0] = g_xh + (size_t)(2 * g + 0) * PLANE + (size_t)row0 * 256;
    aplane[1] = g_xh + (size_t)(2 * g + 1) * PLANE + (size_t)row0 * 256;
    aplane[2] = qin  + (size_t)g * PLANE          + (size_t)row0 * 256;
    const __half* bsrc = wc + (size_t)ncta * 768;

    float* bias_s = reinterpret_cast<float*>(smem + OFF_BIAS);
    if (tid < 128) bias_s[tid] = bias[ncta + tid];

    const uint32_t sb = s2u(smem);
    // per-thread cp.async dst/src decomposition
    const int ldm = tid >> 3, ldt = (tid & 7) * 8;        // row, halfword-col(×8)

    auto loadChunk = [&](int i, int bsel) {
        const __half* sA = aplane[i >> 2] + (i & 3) * 64;
        const uint32_t dA = sb + OFF_A + bsel * 16384;
        #pragma unroll
        for (int it = 0; it < 4; ++it) {           // A: 128 rows x 128B
            int m = ldm + it * 32;
            CPA(dA + SWZ(m * 128 + ldt * 2), sA + (size_t)m * 256 + ldt);
        }
        const __half* sB = bsrc + i * 64;
        const uint32_t dB = sb + OFF_B + bsel * 16384;
        #pragma unroll
        for (int it = 0; it < 4; ++it) {           // B: 128 n-rows x 128B
            int n = ldm + it * 32;
            CPA(dB + SWZ(n * 128 + ldt * 2), sB + (size_t)n * 768 + ldt);
        }
    };

    float c[2][8][4];
    #pragma unroll
    for (int mt = 0; mt < 2; ++mt)
        #pragma unroll
        for (int j = 0; j < 8; ++j)
            #pragma unroll
            for (int e = 0; e < 4; ++e) c[mt][j][e] = 0.0f;

    // per-warp LDSM base offsets (byte addr within buffer, pre-swizzle inputs)
    const int arow = warpM * 32 + (lane & 15);
    const int akb  = (lane >> 4) * 8;
    const int brow = warpN * 64 + ((lane >> 3) & 2) * 4 + (lane & 7);
    const int bkb  = ((lane >> 3) & 1) * 8;

    loadChunk(0, 0); CPC();
    loadChunk(1, 1); CPC();

    uint32_t a[2][2][4], b[2][4][4];

    #pragma unroll 1
    for (int i = 0; i < 12; ++i) {
        const int bsel = i % 3;
        CPW1();
        __syncthreads();
        if (i + 2 < 12) loadChunk(i + 2, (i + 2) % 3);
        CPC();

        const uint32_t aoff = sb + OFF_A + bsel * 16384;
        const uint32_t boff = sb + OFF_B + bsel * 16384;

        // prime ks=0 frags
        #pragma unroll
        for (int mt = 0; mt < 2; ++mt)
            LDSM4(a[0][mt], aoff + SWZ((arow + mt * 16) * 128 + akb * 2));
        #pragma unroll
        for (int j = 0; j < 4; ++j)
            LDSM4(b[0][j], boff + SWZ((brow + j * 16) * 128 + bkb * 2));

        #pragma unroll
        for (int ks = 0; ks < 4; ++ks) {
            const int cur = ks & 1, nxt = cur ^ 1;
            if (ks < 3) {
                const int k0 = (ks + 1) * 16;
                #pragma unroll
                for (int mt = 0; mt < 2; ++mt)
                    LDSM4(a[nxt][mt], aoff + SWZ((arow + mt * 16) * 128 + (k0 + akb) * 2));
                #pragma unroll
                for (int j = 0; j < 4; ++j)
                    LDSM4(b[nxt][j], boff + SWZ((brow + j * 16) * 128 + (k0 + bkb) * 2));
            }
            #pragma unroll
            for (int mt = 0; mt < 2; ++mt)
                #pragma unroll
                for (int j = 0; j < 4; ++j) {
                    MMA(c[mt][2 * j],     a[cur][mt], b[cur][j][0], b[cur][j][1]);
                    MMA(c[mt][2 * j + 1], a[cur][mt], b[cur][j][2], b[cur][j][3]);
                }
        }
    }

    // epilogue: bias + relu (relu for all layers here; final layer's relu is in finalize)
    __half* plane = qout + (size_t)g * PLANE;
    const int do_relu = (layer != 2);
    #pragma unroll
    for (int mt = 0; mt < 2; ++mt) {
        const int r0 = row0 + warpM * 32 + mt * 16 + (lane >> 2);
        #pragma unroll
        for (int j = 0; j < 8; ++j) {
            const int cl = warpN * 64 + j * 8 + (lane & 3) * 2;
            const float b0 = bias_s[cl], b1 = bias_s[cl + 1];
            float v0 = c[mt][j][0] + b0, v1 = c[mt][j][1] + b1;
            float v2 = c[mt][j][2] + b0, v3 = c[mt][j][3] + b1;
            if (do_relu) {
                v0 = fmaxf(v0, 0.0f); v1 = fmaxf(v1, 0.0f);
                v2 = fmaxf(v2, 0.0f); v3 = fmaxf(v3, 0.0f);
            }
            const int gc = ncta + cl;
            *reinterpret_cast<__half2*>(plane + (size_t)r0 * 256 + gc) =
                __floats2half2_rn(v0, v1);
            *reinterpret_cast<__half2*>(plane + (size_t)(r0 + 8) * 256 + gc) =
                __floats2half2_rn(v2, v3);
        }
    }
}

// ---------------- finalize: residual + relu + interleave -------------------
__global__ void finalize_kernel(const float* __restrict__ q, float* __restrict__ out) {
    size_t idx = (size_t)blockIdx.x * 256 + threadIdx.x;
    #pragma unroll
    for (int g = 0; g < 3; ++g) {
        float v = __half2float(g_qa[(size_t)g * PLANE + idx]) + q[idx * 3 + g];
        out[idx * 3 + g] = fmaxf(v, 0.0f);
    }
}

// ---------------- launch ---------------------------------------------------
extern "C" void kernel_launch(void* const* d_in, const int* in_sizes, int n_in,
                              void* d_out, int out_size) {
    const float* x  = (const float*)d_in[0];
    const float* q  = (const float*)d_in[1];
    const float* W1 = (const float*)d_in[2];
    const float* b1 = (const float*)d_in[3];
    const float* W2 = (const float*)d_in[4];
    const float* b2 = (const float*)d_in[5];
    const float* W3 = (const float*)d_in[6];
    const float* b3 = (const float*)d_in[7];
    float* out = (float*)d_out;

    cudaFuncSetAttribute(layer_kernel,
                         cudaFuncAttributeMaxDynamicSharedMemorySize, SMEM_TOTAL);

    prep_xq_kernel<<<NROWS, 256>>>(x, q);
    prep_w_kernel<<<2304, 256>>>(W1, W2, W3);

    dim3 grid(2, 512, 3);
    layer_kernel<<<grid, 256, SMEM_TOTAL>>>(0, 1, b1, 0);  // q0h -> qa, relu
    layer_kernel<<<grid, 256, SMEM_TOTAL>>>(1, 2, b2, 1);  // qa  -> qb, relu
    layer_kernel<<<grid, 256, SMEM_TOTAL>>>(2, 1, b3, 2);  // qb  -> qa, no relu

    finalize_kernel<<<NROWS, 256>>>(q, out);
}